// round 5
// baseline (speedup 1.0000x reference)
#include <cuda_runtime.h>

#define NN   2048
#define MEM  1024
#define NCTA 128
#define TPB  256

typedef unsigned long long ull;

// Persistent device scratch (allocation-free rule: __device__ globals).
__device__ __align__(16) float g_Gx[NN * 5 * MEM];  // 40 MB input projection
__device__ __align__(16) ull g_hp[MEM];             // h payload: (f32, step tag)
__device__ __align__(16) ull g_vp[MEM];             // v payload: (f32, step tag)

__device__ __forceinline__ float sigf(float x) { return 1.0f / (1.0f + expf(-x)); }

__device__ __forceinline__ float warpSum(float v) {
#pragma unroll
    for (int o = 16; o > 0; o >>= 1) v += __shfl_down_sync(0xffffffffu, v, o);
    return v;
}

__device__ __forceinline__ void fma2(ull& acc, ull a, ull b) {
    asm("fma.rn.f32x2 %0, %1, %2, %0;" : "+l"(acc) : "l"(a), "l"(b));
}
__device__ __forceinline__ float2 unpk(ull p) {
    float2 r; asm("mov.b64 {%0,%1}, %2;" : "=f"(r.x), "=f"(r.y) : "l"(p)); return r;
}
__device__ __forceinline__ ull pk(float a, float b) {
    ull p; asm("mov.b64 %0, {%1,%2};" : "=l"(p) : "f"(a), "f"(b)); return p;
}
__device__ __forceinline__ void stcg_u64(ull* p, ull v) {
    asm volatile("st.global.cg.b64 [%0], %1;" :: "l"(p), "l"(v) : "memory");
}

// Cooperative payload acquire: the whole CTA loads 1024 (value, tag) pairs
// (32B/thread), validates every tag block-wide, stages values to smem.
// The payload IS the flag: detection and data arrive in the same L2 trip.
// 8B-aligned pairs are single-copy atomic (no tearing); a stale tag just
// retries. asm volatile forces genuine reloads each round.
__device__ __forceinline__ void stage_validate(const ull* src, float4* dst4,
                                               unsigned tag) {
    const int tid = threadIdx.x;
    const ull* s = src + tid * 4;
    for (;;) {
        unsigned v0, t0, v1, t1, v2, t2, v3, t3;
        asm volatile("ld.global.cg.v4.u32 {%0,%1,%2,%3}, [%4];"
                     : "=r"(v0), "=r"(t0), "=r"(v1), "=r"(t1) : "l"(s));
        asm volatile("ld.global.cg.v4.u32 {%0,%1,%2,%3}, [%4];"
                     : "=r"(v2), "=r"(t2), "=r"(v3), "=r"(t3) : "l"(s + 2));
        const bool ok = (t0 == tag) & (t1 == tag) & (t2 == tag) & (t3 == tag);
        dst4[tid] = make_float4(__uint_as_float(v0), __uint_as_float(v1),
                                __uint_as_float(v2), __uint_as_float(v3));
        if (__syncthreads_and(ok)) break;
    }
}

// ---------------------------------------------------------------------------
// Kernel 1: Gx = inputs @ Wx + bx   (2048 x 1024) @ (1024 x 5120)
// Classic 128x128x8 SGEMM. Block (0,0) also resets the payload tags for this
// graph replay (kernel boundary orders it before the scan).
// ---------------------------------------------------------------------------
__global__ void __launch_bounds__(256) gemm_gx_kernel(
    const float* __restrict__ A,   // inputs (2048,1024)
    const float* __restrict__ B,   // Wx (1024,5120)
    const float* __restrict__ bx)  // (5120,)
{
    if (blockIdx.x == 0 && blockIdx.y == 0) {
        for (int i = threadIdx.x; i < MEM; i += 256) {
            g_hp[i] = 0ull;
            g_vp[i] = 0ull;
        }
    }

    __shared__ float As[8][128];
    __shared__ float Bs[8][132];

    const int tid  = threadIdx.x;
    const int tx   = tid & 15;
    const int ty   = tid >> 4;
    const int arow = tid >> 1;
    const int akc  = (tid & 1) << 2;
    const int bkr  = tid >> 5;
    const int bcol = (tid & 31) << 2;

    const int m0 = blockIdx.y << 7;
    const int n0 = blockIdx.x << 7;

    const float* Aptr = A + (m0 + arow) * 1024 + akc;
    const float* Bptr = B + bkr * 5120 + n0 + bcol;

    float acc[8][8];
#pragma unroll
    for (int i = 0; i < 8; ++i)
#pragma unroll
        for (int j = 0; j < 8; ++j) acc[i][j] = 0.0f;

    for (int kt = 0; kt < 1024; kt += 8) {
        const float4 av = __ldg((const float4*)(Aptr + kt));
        const float4 bv = __ldg((const float4*)(Bptr + kt * 5120));
        As[akc + 0][arow] = av.x;
        As[akc + 1][arow] = av.y;
        As[akc + 2][arow] = av.z;
        As[akc + 3][arow] = av.w;
        *(float4*)&Bs[bkr][bcol] = bv;
        __syncthreads();

#pragma unroll
        for (int k = 0; k < 8; ++k) {
            float ar[8], br[8];
            *(float4*)(ar)     = *(const float4*)&As[k][ty * 8];
            *(float4*)(ar + 4) = *(const float4*)&As[k][ty * 8 + 4];
            *(float4*)(br)     = *(const float4*)&Bs[k][tx * 8];
            *(float4*)(br + 4) = *(const float4*)&Bs[k][tx * 8 + 4];
#pragma unroll
            for (int i = 0; i < 8; ++i)
#pragma unroll
                for (int j = 0; j < 8; ++j) acc[i][j] += ar[i] * br[j];
        }
        __syncthreads();
    }

    const int crow = m0 + ty * 8;
    const int ccol = n0 + tx * 8;
    float bxv[8];
    *(float4*)(bxv)     = __ldg((const float4*)&bx[ccol]);
    *(float4*)(bxv + 4) = __ldg((const float4*)&bx[ccol + 4]);
#pragma unroll
    for (int i = 0; i < 8; ++i) {
        float4 c0 = make_float4(acc[i][0] + bxv[0], acc[i][1] + bxv[1],
                                acc[i][2] + bxv[2], acc[i][3] + bxv[3]);
        float4 c1 = make_float4(acc[i][4] + bxv[4], acc[i][5] + bxv[5],
                                acc[i][6] + bxv[6], acc[i][7] + bxv[7]);
        *(float4*)&g_Gx[(size_t)(crow + i) * 5120 + ccol]     = c0;
        *(float4*)&g_Gx[(size_t)(crow + i) * 5120 + ccol + 4] = c1;
    }
}

// ---------------------------------------------------------------------------
// Kernel 2: persistent scan. 128 CTAs x 8 warps; warp w of CTA b owns state
// dim m = 8b + w (4 Wh gate columns + 1 Wum column, in registers as packed
// f32x2). Publish = one atomic 8-byte (value, tag) store, nothing else.
// Consume = cooperative tag-validated payload load (detection == data).
// No atomics, fences, or counters anywhere on the critical path.
// ---------------------------------------------------------------------------
__global__ void __launch_bounds__(TPB, 1) scan_kernel(
    const float* __restrict__ Wh,  const float* __restrict__ bh,
    const float* __restrict__ Wum, const float* __restrict__ bum,
    const float* __restrict__ pic, const float* __restrict__ pfc,
    const float* __restrict__ poc, const float* __restrict__ pzc,
    float* __restrict__ out)
{
    __shared__ __align__(16) float hbuf[MEM];   // staged h
    __shared__ __align__(16) float vbuf[MEM];   // staged v

    const int tid  = threadIdx.x;
    const int w    = tid >> 5;
    const int lane = tid & 31;
    const int m    = blockIdx.x * 8 + w;        // this warp's state dim

    // ---- load + pack recurrent weights into registers (once) ----
    ulonglong2 wrp[8][4];   // Wh columns {g*MEM+m}, packed pairs over k
    ulonglong2 wmp[8];      // Wum column m
#pragma unroll
    for (int i = 0; i < 8; ++i) {
        const int k = (i * 32 + lane) * 4;
#pragma unroll
        for (int g = 0; g < 4; ++g) {
            const int col = g * MEM + m;
            const float a = __ldg(&Wh[(size_t)(k + 0) * (4 * MEM) + col]);
            const float b = __ldg(&Wh[(size_t)(k + 1) * (4 * MEM) + col]);
            const float c = __ldg(&Wh[(size_t)(k + 2) * (4 * MEM) + col]);
            const float d = __ldg(&Wh[(size_t)(k + 3) * (4 * MEM) + col]);
            wrp[i][g].x = pk(a, b);
            wrp[i][g].y = pk(c, d);
        }
        const float a = __ldg(&Wum[(size_t)(k + 0) * MEM + m]);
        const float b = __ldg(&Wum[(size_t)(k + 1) * MEM + m]);
        const float c = __ldg(&Wum[(size_t)(k + 2) * MEM + m]);
        const float d = __ldg(&Wum[(size_t)(k + 3) * MEM + m]);
        wmp[i].x = pk(a, b);
        wmp[i].y = pk(c, d);
    }

    // per-dim constants (used by lane 0 of each warp)
    float bh_i = 0, bh_o = 0, bh_f = 0, bh_z = 0, bum_v = 0;
    float pic_v = 0, pfc_v = 0, poc_v = 0, pzc_v = 0;
    if (lane == 0) {
        bh_i = bh[m];           bh_o = bh[MEM + m];
        bh_f = bh[2 * MEM + m]; bh_z = bh[3 * MEM + m];
        bum_v = bum[m];
        pic_v = pic[m]; pfc_v = pfc[m]; poc_v = poc[m]; pzc_v = pzc[m];
    }
    float cp = 0.0f, hmx = -3.402823466e38f;

#pragma unroll 1
    for (unsigned t = 0; t < NN; ++t) {
        // Gx prefetch (independent of sync; hides under the payload acquire)
        float gxi = 0, gxo = 0, gxf = 0, gxz = 0, gxu = 0;
        if (lane == 0) {
            const float* gx = g_Gx + (size_t)t * (5 * MEM) + m;
            gxi = __ldg(gx);
            gxo = __ldg(gx + MEM);
            gxf = __ldg(gx + 2 * MEM);
            gxz = __ldg(gx + 3 * MEM);
            gxu = __ldg(gx + 4 * MEM);
        }

        // ---- acquire h(t-1) (carries tag t) ----
        if (t == 0) {
            ((float4*)hbuf)[tid] = make_float4(0.f, 0.f, 0.f, 0.f);
            __syncthreads();
        } else {
            stage_validate(g_hp, (float4*)hbuf, t);
        }

        // ---- phase 1: 4 gate-column dots + gates, publish v ----
        ull acc[4][2] = {{0ull, 0ull}, {0ull, 0ull}, {0ull, 0ull}, {0ull, 0ull}};
        const ulonglong2* hp2 = (const ulonglong2*)hbuf;
#pragma unroll
        for (int i = 0; i < 8; ++i) {
            const ulonglong2 hp = hp2[i * 32 + lane];
#pragma unroll
            for (int g = 0; g < 4; ++g) {
                fma2(acc[g][0], hp.x, wrp[i][g].x);
                fma2(acc[g][1], hp.y, wrp[i][g].y);
            }
        }
        float2 e0 = unpk(acc[0][0]), o0 = unpk(acc[0][1]);
        float2 e1 = unpk(acc[1][0]), o1 = unpk(acc[1][1]);
        float2 e2 = unpk(acc[2][0]), o2 = unpk(acc[2][1]);
        float2 e3 = unpk(acc[3][0]), o3 = unpk(acc[3][1]);
        const float s0 = warpSum(e0.x + e0.y + o0.x + o0.y);
        const float s1 = warpSum(e1.x + e1.y + o1.x + o1.y);
        const float s2 = warpSum(e2.x + e2.y + o2.x + o2.y);
        const float s3 = warpSum(e3.x + e3.y + o3.x + o3.y);

        float iv = 0.f, fv = 0.f, opre = 0.f;
        if (lane == 0) {
            iv   = sigf(gxi + s0 + bh_i + pic_v * cp);
            fv   = sigf(gxf + s2 + bh_f + pfc_v * cp);
            const float zv = sigf(gxz + s3 + bh_z + pzc_v * cp);
            opre = gxo + s1 + bh_o;
            const float vv = zv * tanhf(cp);
            stcg_u64(&g_vp[m], ((ull)(t + 1) << 32) | (ull)__float_as_uint(vv));
        }

        // ---- acquire v(t) (carries tag t+1) ----
        stage_validate(g_vp, (float4*)vbuf, t + 1);

        // ---- phase 2: Wum dot, u/c/o/h, publish h ----
        ull b0 = 0ull, b1 = 0ull;
        const ulonglong2* vp2 = (const ulonglong2*)vbuf;
#pragma unroll
        for (int i = 0; i < 8; ++i) {
            const ulonglong2 vp = vp2[i * 32 + lane];
            fma2(b0, vp.x, wmp[i].x);
            fma2(b1, vp.y, wmp[i].y);
        }
        float2 be = unpk(b0), bo = unpk(b1);
        const float sb = warpSum(be.x + be.y + bo.x + bo.y);

        if (lane == 0) {
            const float u  = tanhf(gxu + sb + bum_v);
            const float c  = iv * u + fv * cp;
            const float oo = sigf(opre + poc_v * c);
            const float hh = oo * tanhf(c);
            cp  = c;
            hmx = fmaxf(hmx, hh);
            stcg_u64(&g_hp[m], ((ull)(t + 1) << 32) | (ull)__float_as_uint(hh));
        }
    }

    if (lane == 0) out[m] = hmx;
}

// ---------------------------------------------------------------------------
extern "C" void kernel_launch(void* const* d_in, const int* in_sizes, int n_in,
                              void* d_out, int out_size) {
    const float* inputs = (const float*)d_in[0];
    const float* Wx     = (const float*)d_in[1];
    const float* bx     = (const float*)d_in[2];
    const float* Wh     = (const float*)d_in[3];
    const float* bh     = (const float*)d_in[4];
    const float* Wum    = (const float*)d_in[5];
    const float* bum    = (const float*)d_in[6];
    const float* pic    = (const float*)d_in[7];
    const float* pfc    = (const float*)d_in[8];
    const float* poc    = (const float*)d_in[9];
    const float* pzc    = (const float*)d_in[10];
    float* out = (float*)d_out;

    dim3 gg(5120 / 128, 2048 / 128);
    gemm_gx_kernel<<<gg, 256>>>(inputs, Wx, bx);
    scan_kernel<<<NCTA, TPB>>>(Wh, bh, Wum, bum,
                               pic, pfc, poc, pzc, out);
}

// round 9
// speedup vs baseline: 2.5866x; 2.5866x over previous
#include <cuda_runtime.h>

#define NN   2048
#define MEM  1024
#define NCTA 128
#define TPB  256

typedef unsigned long long ull;

// Persistent device scratch (allocation-free rule: __device__ globals).
__device__ __align__(16) float g_Gx[NN * 5 * MEM];  // 40 MB input projection
__device__ __align__(16) float g_h[MEM];            // recurrent hidden broadcast
__device__ __align__(16) float g_v[MEM];            // z*tanh(c) broadcast
__device__ __align__(128) unsigned g_bar;           // single arrival counter

__device__ __forceinline__ float sigf(float x) { return 1.0f / (1.0f + expf(-x)); }

__device__ __forceinline__ float warpSum(float v) {
#pragma unroll
    for (int o = 16; o > 0; o >>= 1) v += __shfl_down_sync(0xffffffffu, v, o);
    return v;
}

__device__ __forceinline__ void fma2(ull& acc, ull a, ull b) {
    asm("fma.rn.f32x2 %0, %1, %2, %0;" : "+l"(acc) : "l"(a), "l"(b));
}
__device__ __forceinline__ float2 unpk(ull p) {
    float2 r; asm("mov.b64 {%0,%1}, %2;" : "=f"(r.x), "=f"(r.y) : "l"(p)); return r;
}
__device__ __forceinline__ ull pk(float a, float b) {
    ull p; asm("mov.b64 %0, {%1,%2};" : "=l"(p) : "f"(a), "f"(b)); return p;
}
__device__ __forceinline__ unsigned ld_acquire_u32(const unsigned* p) {
    unsigned v;
    asm volatile("ld.acquire.gpu.global.u32 %0, [%1];" : "=r"(v) : "l"(p));
    return v;
}
__device__ __forceinline__ void red_release_add(unsigned* p, unsigned v) {
    asm volatile("red.release.gpu.global.add.u32 [%0], %1;" :: "l"(p), "r"(v)
                 : "memory");
}
__device__ __forceinline__ void stcg_f4(float* p, float4 v) {
    asm volatile("st.global.cg.v4.f32 [%0], {%1,%2,%3,%4};"
                 :: "l"(p), "f"(v.x), "f"(v.y), "f"(v.z), "f"(v.w) : "memory");
}

// ---------------------------------------------------------------------------
// Kernel 1: Gx = inputs @ Wx + bx   (2048 x 1024) @ (1024 x 5120)
// Classic 128x128x8 SGEMM. Block (0,0) also resets the arrival counter for
// this graph replay (kernel boundary orders it before the scan).
// ---------------------------------------------------------------------------
__global__ void __launch_bounds__(256) gemm_gx_kernel(
    const float* __restrict__ A,   // inputs (2048,1024)
    const float* __restrict__ B,   // Wx (1024,5120)
    const float* __restrict__ bx)  // (5120,)
{
    if (blockIdx.x == 0 && blockIdx.y == 0 && threadIdx.x == 0) g_bar = 0u;

    __shared__ float As[8][128];
    __shared__ float Bs[8][132];

    const int tid  = threadIdx.x;
    const int tx   = tid & 15;
    const int ty   = tid >> 4;
    const int arow = tid >> 1;
    const int akc  = (tid & 1) << 2;
    const int bkr  = tid >> 5;
    const int bcol = (tid & 31) << 2;

    const int m0 = blockIdx.y << 7;
    const int n0 = blockIdx.x << 7;

    const float* Aptr = A + (m0 + arow) * 1024 + akc;
    const float* Bptr = B + bkr * 5120 + n0 + bcol;

    float acc[8][8];
#pragma unroll
    for (int i = 0; i < 8; ++i)
#pragma unroll
        for (int j = 0; j < 8; ++j) acc[i][j] = 0.0f;

    for (int kt = 0; kt < 1024; kt += 8) {
        const float4 av = __ldg((const float4*)(Aptr + kt));
        const float4 bv = __ldg((const float4*)(Bptr + kt * 5120));
        As[akc + 0][arow] = av.x;
        As[akc + 1][arow] = av.y;
        As[akc + 2][arow] = av.z;
        As[akc + 3][arow] = av.w;
        *(float4*)&Bs[bkr][bcol] = bv;
        __syncthreads();

#pragma unroll
        for (int k = 0; k < 8; ++k) {
            float ar[8], br[8];
            *(float4*)(ar)     = *(const float4*)&As[k][ty * 8];
            *(float4*)(ar + 4) = *(const float4*)&As[k][ty * 8 + 4];
            *(float4*)(br)     = *(const float4*)&Bs[k][tx * 8];
            *(float4*)(br + 4) = *(const float4*)&Bs[k][tx * 8 + 4];
#pragma unroll
            for (int i = 0; i < 8; ++i)
#pragma unroll
                for (int j = 0; j < 8; ++j) acc[i][j] += ar[i] * br[j];
        }
        __syncthreads();
    }

    const int crow = m0 + ty * 8;
    const int ccol = n0 + tx * 8;
    float bxv[8];
    *(float4*)(bxv)     = __ldg((const float4*)&bx[ccol]);
    *(float4*)(bxv + 4) = __ldg((const float4*)&bx[ccol + 4]);
#pragma unroll
    for (int i = 0; i < 8; ++i) {
        float4 c0 = make_float4(acc[i][0] + bxv[0], acc[i][1] + bxv[1],
                                acc[i][2] + bxv[2], acc[i][3] + bxv[3]);
        float4 c1 = make_float4(acc[i][4] + bxv[4], acc[i][5] + bxv[5],
                                acc[i][6] + bxv[6], acc[i][7] + bxv[7]);
        *(float4*)&g_Gx[(size_t)(crow + i) * 5120 + ccol]     = c0;
        *(float4*)&g_Gx[(size_t)(crow + i) * 5120 + ccol + 4] = c1;
    }
}

// ---------------------------------------------------------------------------
// Kernel 2: persistent scan. 128 CTAs x 8 warps; warp w of CTA b owns state
// dim m = 8b + w (4 Wh gate columns + 1 Wum column in registers, packed
// f32x2). Sync topology is the round-3-proven one: per phase, thread 0 alone
// stores the CTA's 8 output floats (st.cg) and fires ONE red.release (same-
// thread ordering), and thread 0 alone polls the single counter with
// ld.acquire. Valid: all 128 CTAs co-resident (238 regs, 4KB smem -> every
// SM hosts a CTA; 128 <= 148 SMs).
// ---------------------------------------------------------------------------
__global__ void __launch_bounds__(TPB, 1) scan_kernel(
    const float* __restrict__ Wh,  const float* __restrict__ bh,
    const float* __restrict__ Wum, const float* __restrict__ bum,
    const float* __restrict__ pic, const float* __restrict__ pfc,
    const float* __restrict__ poc, const float* __restrict__ pzc,
    float* __restrict__ out)
{
    __shared__ __align__(16) float xbuf[MEM];   // broadcast h (ph1) / v (ph2)
    __shared__ __align__(16) float ssh[8];      // per-warp publish staging

    const int tid  = threadIdx.x;
    const int w    = tid >> 5;
    const int lane = tid & 31;
    const int m0   = blockIdx.x * 8;
    const int m    = m0 + w;                    // this warp's state dim

    // ---- load + pack recurrent weights into registers (once) ----
    ulonglong2 wrp[8][4];   // Wh columns {g*MEM+m}, packed pairs over k
    ulonglong2 wmp[8];      // Wum column m
#pragma unroll
    for (int i = 0; i < 8; ++i) {
        const int k = (i * 32 + lane) * 4;
#pragma unroll
        for (int g = 0; g < 4; ++g) {
            const int col = g * MEM + m;
            const float a = __ldg(&Wh[(size_t)(k + 0) * (4 * MEM) + col]);
            const float b = __ldg(&Wh[(size_t)(k + 1) * (4 * MEM) + col]);
            const float c = __ldg(&Wh[(size_t)(k + 2) * (4 * MEM) + col]);
            const float d = __ldg(&Wh[(size_t)(k + 3) * (4 * MEM) + col]);
            wrp[i][g].x = pk(a, b);
            wrp[i][g].y = pk(c, d);
        }
        const float a = __ldg(&Wum[(size_t)(k + 0) * MEM + m]);
        const float b = __ldg(&Wum[(size_t)(k + 1) * MEM + m]);
        const float c = __ldg(&Wum[(size_t)(k + 2) * MEM + m]);
        const float d = __ldg(&Wum[(size_t)(k + 3) * MEM + m]);
        wmp[i].x = pk(a, b);
        wmp[i].y = pk(c, d);
    }

    // per-dim constants (used by lane 0 of each warp)
    float bh_i = 0, bh_o = 0, bh_f = 0, bh_z = 0, bum_v = 0;
    float pic_v = 0, pfc_v = 0, poc_v = 0, pzc_v = 0;
    if (lane == 0) {
        bh_i = bh[m];           bh_o = bh[MEM + m];
        bh_f = bh[2 * MEM + m]; bh_z = bh[3 * MEM + m];
        bum_v = bum[m];
        pic_v = pic[m]; pfc_v = pfc[m]; poc_v = poc[m]; pzc_v = pzc[m];
    }
    float cp = 0.0f, hmx = -3.402823466e38f;

    float4* xbuf4 = (float4*)xbuf;
    __syncthreads();

#pragma unroll 1
    for (unsigned t = 0; t < NN; ++t) {
        // Gx prefetch (independent of sync; hides under the poll)
        float gxi = 0, gxo = 0, gxf = 0, gxz = 0, gxu = 0;
        if (lane == 0) {
            const float* gx = g_Gx + (size_t)t * (5 * MEM) + m;
            gxi = __ldg(gx);
            gxo = __ldg(gx + MEM);
            gxf = __ldg(gx + 2 * MEM);
            gxz = __ldg(gx + 3 * MEM);
            gxu = __ldg(gx + 4 * MEM);
        }

        // ---- acquire h(t-1) ----
        if (t == 0) {
            xbuf4[tid] = make_float4(0.f, 0.f, 0.f, 0.f);
        } else {
            if (tid == 0) while (ld_acquire_u32(&g_bar) < 256u * t) { }
            __syncthreads();
            xbuf4[tid] = __ldcg(((const float4*)g_h) + tid);
        }
        __syncthreads();

        // ---- phase 1: 4 gate-column dots + gates, publish v ----
        ull acc[4][2] = {{0ull, 0ull}, {0ull, 0ull}, {0ull, 0ull}, {0ull, 0ull}};
        const ulonglong2* hp2 = (const ulonglong2*)xbuf;
#pragma unroll
        for (int i = 0; i < 8; ++i) {
            const ulonglong2 hp = hp2[i * 32 + lane];
#pragma unroll
            for (int g = 0; g < 4; ++g) {
                fma2(acc[g][0], hp.x, wrp[i][g].x);
                fma2(acc[g][1], hp.y, wrp[i][g].y);
            }
        }
        float2 e0 = unpk(acc[0][0]), o0 = unpk(acc[0][1]);
        float2 e1 = unpk(acc[1][0]), o1 = unpk(acc[1][1]);
        float2 e2 = unpk(acc[2][0]), o2 = unpk(acc[2][1]);
        float2 e3 = unpk(acc[3][0]), o3 = unpk(acc[3][1]);
        const float s0 = warpSum(e0.x + e0.y + o0.x + o0.y);
        const float s1 = warpSum(e1.x + e1.y + o1.x + o1.y);
        const float s2 = warpSum(e2.x + e2.y + o2.x + o2.y);
        const float s3 = warpSum(e3.x + e3.y + o3.x + o3.y);

        float iv = 0.f, fv = 0.f, opre = 0.f;
        if (lane == 0) {
            iv   = sigf(gxi + s0 + bh_i + pic_v * cp);
            fv   = sigf(gxf + s2 + bh_f + pfc_v * cp);
            const float zv = sigf(gxz + s3 + bh_z + pzc_v * cp);
            opre = gxo + s1 + bh_o;
            ssh[w] = zv * tanhf(cp);
        }
        __syncthreads();
        if (tid == 0) {
            stcg_f4(&g_v[m0],     *(float4*)&ssh[0]);
            stcg_f4(&g_v[m0 + 4], *(float4*)&ssh[4]);
            red_release_add(&g_bar, 1u);   // same-thread release orders stores
            while (ld_acquire_u32(&g_bar) < 256u * t + 128u) { }
        }
        __syncthreads();

        // ---- acquire v(t), phase 2: Wum dot, u/c/o/h, publish h ----
        xbuf4[tid] = __ldcg(((const float4*)g_v) + tid);
        __syncthreads();

        ull b0 = 0ull, b1 = 0ull;
        const ulonglong2* vp2 = (const ulonglong2*)xbuf;
#pragma unroll
        for (int i = 0; i < 8; ++i) {
            const ulonglong2 vp = vp2[i * 32 + lane];
            fma2(b0, vp.x, wmp[i].x);
            fma2(b1, vp.y, wmp[i].y);
        }
        float2 be = unpk(b0), bo = unpk(b1);
        const float sb = warpSum(be.x + be.y + bo.x + bo.y);

        if (lane == 0) {
            const float u  = tanhf(gxu + sb + bum_v);
            const float c  = iv * u + fv * cp;
            const float oo = sigf(opre + poc_v * c);
            const float hh = oo * tanhf(c);
            cp  = c;
            hmx = fmaxf(hmx, hh);
            ssh[w] = hh;
        }
        __syncthreads();
        if (tid == 0) {
            stcg_f4(&g_h[m0],     *(float4*)&ssh[0]);
            stcg_f4(&g_h[m0 + 4], *(float4*)&ssh[4]);
            red_release_add(&g_bar, 1u);
        }
        // next iteration's h-acquire performs the poll for 256*(t+1)
    }

    if (lane == 0) out[m] = hmx;
}

// ---------------------------------------------------------------------------
extern "C" void kernel_launch(void* const* d_in, const int* in_sizes, int n_in,
                              void* d_out, int out_size) {
    const float* inputs = (const float*)d_in[0];
    const float* Wx     = (const float*)d_in[1];
    const float* bx     = (const float*)d_in[2];
    const float* Wh     = (const float*)d_in[3];
    const float* bh     = (const float*)d_in[4];
    const float* Wum    = (const float*)d_in[5];
    const float* bum    = (const float*)d_in[6];
    const float* pic    = (const float*)d_in[7];
    const float* pfc    = (const float*)d_in[8];
    const float* poc    = (const float*)d_in[9];
    const float* pzc    = (const float*)d_in[10];
    float* out = (float*)d_out;

    dim3 gg(5120 / 128, 2048 / 128);
    gemm_gx_kernel<<<gg, 256>>>(inputs, Wx, bx);
    scan_kernel<<<NCTA, TPB>>>(Wh, bh, Wum, bum,
                               pic, pfc, poc, pzc, out);
}